// round 2
// baseline (speedup 1.0000x reference)
#include <cuda_runtime.h>
#include <math.h>

// Problem constants
#define T_   4096
#define B_   32
#define I_   128
#define H_   128
#define TB_  (T_*B_)      // 131072 rows
#define G4_  (4*H_)       // 512 gate columns total

// Main-kernel tiling
#define MT  128           // rows per CTA
#define NT  128           // gate columns per CTA (32 heads x 4 gates)
#define KD  128           // full K staged once
#define LDA (KD+4)        // A smem row stride (floats), keeps 16B alignment
#define LDW (NT+4)        // W smem row stride

// Scratch (device globals -- no allocation allowed)
__device__ float g_hb[B_*G4_];          // Hb[b][g] = h0@W_hh^T + b_ih + b_hh
__device__ float g_warr[4*KD*NT];       // [ht][k][n], n = head_local*4 + gate

// ---------------- packed f32x2 helpers (Blackwell FFMA2 path) ----------------
#define PACK2(d, x, y) \
    asm("mov.b64 %0, {%1, %2};" : "=l"(d) : "r"(__float_as_uint(x)), "r"(__float_as_uint(y)))
#define UNPACK2(x, y, s) do { unsigned _lo, _hi; \
    asm("mov.b64 {%0, %1}, %2;" : "=r"(_lo), "=r"(_hi) : "l"(s)); \
    (x) = __uint_as_float(_lo); (y) = __uint_as_float(_hi); } while (0)
#define FMA2(accv, av, wv) \
    asm("fma.rn.f32x2 %0, %1, %2, %0;" : "+l"(accv) : "l"(av), "l"(wv))

// ---------------- prep: Hb = h0 @ W_hh^T + b_ih + b_hh ----------------
__global__ void prep_hb(const float* __restrict__ h0, const float* __restrict__ W_hh,
                        const float* __restrict__ b_ih, const float* __restrict__ b_hh) {
    int g = threadIdx.x;          // 0..511
    int b = blockIdx.x;           // 0..31
    float s = b_ih[g] + b_hh[g];
    const float* hr = h0 + b * H_;
    const float* wr = W_hh + g * H_;
#pragma unroll 8
    for (int k = 0; k < H_; k++) s += hr[k] * wr[k];
    g_hb[b * G4_ + g] = s;
}

// ---------------- prep: rearrange W_ih into [ht][k][n] gate-interleaved ----------------
// n = hl*4 + q  (hl = head within 32-head tile, q = gate 0..3)
// global gate row: g = q*128 + ht*32 + hl
__global__ void prep_w(const float* __restrict__ W_ih) {
    int idx = blockIdx.x * 256 + threadIdx.x;   // 0 .. 65535
    int ht  = idx >> 14;
    int rem = idx & 16383;
    int k   = rem >> 7;
    int n   = rem & 127;
    int q   = n & 3;
    int hl  = n >> 2;
    int g   = q * H_ + ht * 32 + hl;
    g_warr[idx] = W_ih[g * I_ + k];
}

// ---------------- main fused kernel ----------------
__global__ __launch_bounds__(256, 1)
void lstm_main(const float* __restrict__ input, const float* __restrict__ c0,
               const float* __restrict__ noise, float* __restrict__ out) {
    extern __shared__ float sm[];
    float* As  = sm;                       // MT*LDA   A tile, [m][k]
    float* Ws  = As + MT * LDA;            // KD*LDW   W tile, [k][n]
    float* HBs = Ws + KD * LDW;            // 32*128   Hb staged for this ht
    float* C0s = HBs + B_ * NT;            // 32*32
    float* NZs = C0s + B_ * 32;            // 32*32

    const int  tid = threadIdx.x;
    const int  ht  = blockIdx.x;                 // 0..3 head tile
    const long r0  = (long)blockIdx.y * MT;      // first row

    // --- stage A tile (coalesced float4, natural [m][k] layout) ---
    const float4* inp4 = (const float4*)(input + r0 * I_);
#pragma unroll
    for (int it = 0; it < 16; it++) {
        int idx = tid + it * 256;            // m*32 + kq
        int m = idx >> 5, kq = idx & 31;
        float4 v = inp4[idx];
        *(float4*)(As + m * LDA + kq * 4) = v;
    }
    // --- stage W tile (already [k][n] in g_warr, coalesced) ---
    const float4* w4 = (const float4*)(g_warr + ht * (KD * NT));
#pragma unroll
    for (int it = 0; it < 16; it++) {
        int idx = tid + it * 256;            // k*32 + nq
        int k = idx >> 5, nq = idx & 31;
        float4 v = w4[idx];
        *(float4*)(Ws + k * LDW + nq * 4) = v;
    }
    // --- stage Hb for this head tile: HBs[b][n] ---
#pragma unroll
    for (int it = 0; it < 16; it++) {
        int idx = tid + it * 256;            // b*128 + n
        int b = idx >> 7, n = idx & 127;
        int g = (n & 3) * H_ + ht * 32 + (n >> 2);
        HBs[idx] = g_hb[b * G4_ + g];
    }
    // --- stage c0/noise slices: [b][hl] for hl in this head tile ---
#pragma unroll
    for (int it = 0; it < 4; it++) {
        int idx = tid + it * 256;            // b*32 + hl
        int b = idx >> 5, hl = idx & 31;
        C0s[idx] = c0[b * H_ + ht * 32 + hl];
        NZs[idx] = noise[b * H_ + ht * 32 + hl];
    }
    __syncthreads();

    const int tx = tid & 15, ty = tid >> 4;      // 16 x 16 thread grid
    const float* Ab = As + (ty * 8) * LDA;
    const float* Wb = Ws + tx * 8;

    unsigned long long acc[8][4];                // 8 rows x 4 col-pairs (packed f32x2)
#pragma unroll
    for (int i = 0; i < 8; i++)
#pragma unroll
        for (int p = 0; p < 4; p++) acc[i][p] = 0ull;

#pragma unroll 4
    for (int k = 0; k < KD; k += 2) {
        float2 a[8];
#pragma unroll
        for (int i = 0; i < 8; i++) a[i] = *(const float2*)(Ab + i * LDA + k);
        float4 w0a = *(const float4*)(Wb + k * LDW);
        float4 w0b = *(const float4*)(Wb + k * LDW + 4);
        float4 w1a = *(const float4*)(Wb + (k + 1) * LDW);
        float4 w1b = *(const float4*)(Wb + (k + 1) * LDW + 4);
        unsigned long long w0[4], w1[4];
        PACK2(w0[0], w0a.x, w0a.y); PACK2(w0[1], w0a.z, w0a.w);
        PACK2(w0[2], w0b.x, w0b.y); PACK2(w0[3], w0b.z, w0b.w);
        PACK2(w1[0], w1a.x, w1a.y); PACK2(w1[1], w1a.z, w1a.w);
        PACK2(w1[2], w1b.x, w1b.y); PACK2(w1[3], w1b.z, w1b.w);
#pragma unroll
        for (int i = 0; i < 8; i++) {
            unsigned long long a0, a1;
            PACK2(a0, a[i].x, a[i].x);
            PACK2(a1, a[i].y, a[i].y);
            FMA2(acc[i][0], a0, w0[0]);
            FMA2(acc[i][1], a0, w0[1]);
            FMA2(acc[i][2], a0, w0[2]);
            FMA2(acc[i][3], a0, w0[3]);
            FMA2(acc[i][0], a1, w1[0]);
            FMA2(acc[i][1], a1, w1[1]);
            FMA2(acc[i][2], a1, w1[2]);
            FMA2(acc[i][3], a1, w1[3]);
        }
    }

    // --- fused LSTM-cell epilogue ---
    const int nb = tx * 8;                   // first gate-col of this thread
#pragma unroll
    for (int i = 0; i < 8; i++) {
        long r = r0 + ty * 8 + i;
        int  b = (int)(r & (B_ - 1));        // row r = t*B + b
        float v[8];
#pragma unroll
        for (int p = 0; p < 4; p++) UNPACK2(v[2 * p], v[2 * p + 1], acc[i][p]);
        float hv[2], cv[2];
#pragma unroll
        for (int hh = 0; hh < 2; hh++) {
            const float* hb = HBs + b * NT + nb + hh * 4;
            float gi = v[hh * 4 + 0] + hb[0];
            float gf = v[hh * 4 + 1] + hb[1];
            float gg = v[hh * 4 + 2] + hb[2];
            float go = v[hh * 4 + 3] + hb[3];
            float si = 1.f / (1.f + expf(-gi));
            float sf = 1.f / (1.f + expf(-gf));
            float tg = tanhf(gg);
            float so = 1.f / (1.f + expf(-go));
            int hl = tx * 2 + hh;
            float c = sf * C0s[b * 32 + hl] + si * tg;
            cv[hh] = c;
            hv[hh] = so * tanhf(c) + NZs[b * 32 + hl];
        }
        float2 hp = make_float2(hv[0], hv[1]);
        long obase = r * H_ + ht * 32 + tx * 2;
        *(float2*)(out + obase) = hp;
        if (r >= (long)TB_ - B_) {           // last timestep: also h_last, c_last
            long lb = (long)TB_ * H_ + (long)b * H_ + ht * 32 + tx * 2;
            *(float2*)(out + lb) = hp;
            *(float2*)(out + lb + B_ * H_) = make_float2(cv[0], cv[1]);
        }
    }
}

// ---------------- launch ----------------
extern "C" void kernel_launch(void* const* d_in, const int* in_sizes, int n_in,
                              void* d_out, int out_size) {
    const float* input = (const float*)d_in[0];
    const float* h0    = (const float*)d_in[1];
    const float* c0    = (const float*)d_in[2];
    const float* noise = (const float*)d_in[3];
    const float* W_ih  = (const float*)d_in[4];
    const float* W_hh  = (const float*)d_in[5];
    const float* b_ih  = (const float*)d_in[6];
    const float* b_hh  = (const float*)d_in[7];
    float* out = (float*)d_out;

    prep_hb<<<B_, G4_>>>(h0, W_hh, b_ih, b_hh);
    prep_w<<<256, 256>>>(W_ih);

    const int smem = (MT * LDA + KD * LDW + B_ * NT + B_ * 32 + B_ * 32) * (int)sizeof(float);
    cudaFuncSetAttribute(lstm_main, cudaFuncAttributeMaxDynamicSharedMemorySize, smem);

    dim3 grid(4, TB_ / MT);   // 4 head tiles x 1024 row tiles
    lstm_main<<<grid, 256, smem>>>(input, c0, noise, out);
}

// round 3
// speedup vs baseline: 1.0009x; 1.0009x over previous
#include <cuda_runtime.h>
#include <math.h>

// Problem constants
#define T_   4096
#define B_   32
#define I_   128
#define H_   128
#define TB_  (T_*B_)      // 131072 rows
#define G4_  (4*H_)       // 512 gate columns total

// Main-kernel tiling
#define MT  128           // rows per CTA
#define NT  128           // gate columns per CTA (32 heads x 4 gates)
#define KD  128           // full K staged once
#define LDA (KD+4)        // A smem row stride (floats), keeps 16B alignment
#define LDW (NT+4)        // W smem row stride

// Scratch (device globals -- no allocation allowed)
__device__ float g_hb[B_*G4_];          // Hb[b][g] = h0@W_hh^T + b_ih + b_hh
__device__ float g_warr[4*KD*NT];       // [ht][k][n], n = head_local*4 + gate

// ---------------- packed f32x2 helpers (Blackwell FFMA2 path) ----------------
#define PACK2(d, x, y) \
    asm("mov.b64 %0, {%1, %2};" : "=l"(d) : "r"(__float_as_uint(x)), "r"(__float_as_uint(y)))
#define UNPACK2(x, y, s) do { unsigned _lo, _hi; \
    asm("mov.b64 {%0, %1}, %2;" : "=r"(_lo), "=r"(_hi) : "l"(s)); \
    (x) = __uint_as_float(_lo); (y) = __uint_as_float(_hi); } while (0)
#define FMA2(accv, av, wv) \
    asm("fma.rn.f32x2 %0, %1, %2, %0;" : "+l"(accv) : "l"(av), "l"(wv))

// ---------------- prep: Hb = h0 @ W_hh^T + b_ih + b_hh ----------------
__global__ void prep_hb(const float* __restrict__ h0, const float* __restrict__ W_hh,
                        const float* __restrict__ b_ih, const float* __restrict__ b_hh) {
    int g = threadIdx.x;          // 0..511
    int b = blockIdx.x;           // 0..31
    float s = b_ih[g] + b_hh[g];
    const float* hr = h0 + b * H_;
    const float* wr = W_hh + g * H_;
#pragma unroll 8
    for (int k = 0; k < H_; k++) s += hr[k] * wr[k];
    g_hb[b * G4_ + g] = s;
}

// ---------------- prep: rearrange W_ih into [ht][k][n] gate-interleaved ----------------
// n = hl*4 + q  (hl = head within 32-head tile, q = gate 0..3)
// global gate row: g = q*128 + ht*32 + hl
__global__ void prep_w(const float* __restrict__ W_ih) {
    int idx = blockIdx.x * 256 + threadIdx.x;   // 0 .. 65535
    int ht  = idx >> 14;
    int rem = idx & 16383;
    int k   = rem >> 7;
    int n   = rem & 127;
    int q   = n & 3;
    int hl  = n >> 2;
    int g   = q * H_ + ht * 32 + hl;
    g_warr[idx] = W_ih[g * I_ + k];
}

// ---------------- main fused kernel ----------------
__global__ __launch_bounds__(256, 1)
void lstm_main(const float* __restrict__ input, const float* __restrict__ c0,
               const float* __restrict__ noise, float* __restrict__ out) {
    extern __shared__ float sm[];
    float* As  = sm;                       // MT*LDA   A tile, [m][k]
    float* Ws  = As + MT * LDA;            // KD*LDW   W tile, [k][n]
    float* HBs = Ws + KD * LDW;            // 32*128   Hb staged for this ht
    float* C0s = HBs + B_ * NT;            // 32*32
    float* NZs = C0s + B_ * 32;            // 32*32

    const int  tid = threadIdx.x;
    const int  ht  = blockIdx.x;                 // 0..3 head tile
    const long r0  = (long)blockIdx.y * MT;      // first row

    // --- stage A tile (coalesced float4, natural [m][k] layout) ---
    const float4* inp4 = (const float4*)(input + r0 * I_);
#pragma unroll
    for (int it = 0; it < 16; it++) {
        int idx = tid + it * 256;            // m*32 + kq
        int m = idx >> 5, kq = idx & 31;
        float4 v = inp4[idx];
        *(float4*)(As + m * LDA + kq * 4) = v;
    }
    // --- stage W tile (already [k][n] in g_warr, coalesced) ---
    const float4* w4 = (const float4*)(g_warr + ht * (KD * NT));
#pragma unroll
    for (int it = 0; it < 16; it++) {
        int idx = tid + it * 256;            // k*32 + nq
        int k = idx >> 5, nq = idx & 31;
        float4 v = w4[idx];
        *(float4*)(Ws + k * LDW + nq * 4) = v;
    }
    // --- stage Hb for this head tile: HBs[b][n] ---
#pragma unroll
    for (int it = 0; it < 16; it++) {
        int idx = tid + it * 256;            // b*128 + n
        int b = idx >> 7, n = idx & 127;
        int g = (n & 3) * H_ + ht * 32 + (n >> 2);
        HBs[idx] = g_hb[b * G4_ + g];
    }
    // --- stage c0/noise slices: [b][hl] for hl in this head tile ---
#pragma unroll
    for (int it = 0; it < 4; it++) {
        int idx = tid + it * 256;            // b*32 + hl
        int b = idx >> 5, hl = idx & 31;
        C0s[idx] = c0[b * H_ + ht * 32 + hl];
        NZs[idx] = noise[b * H_ + ht * 32 + hl];
    }
    __syncthreads();

    const int tx = tid & 15, ty = tid >> 4;      // 16 x 16 thread grid
    const float* Ab = As + (ty * 8) * LDA;
    const float* Wb = Ws + tx * 8;

    unsigned long long acc[8][4];                // 8 rows x 4 col-pairs (packed f32x2)
#pragma unroll
    for (int i = 0; i < 8; i++)
#pragma unroll
        for (int p = 0; p < 4; p++) acc[i][p] = 0ull;

#pragma unroll 4
    for (int k = 0; k < KD; k += 2) {
        float2 a[8];
#pragma unroll
        for (int i = 0; i < 8; i++) a[i] = *(const float2*)(Ab + i * LDA + k);
        float4 w0a = *(const float4*)(Wb + k * LDW);
        float4 w0b = *(const float4*)(Wb + k * LDW + 4);
        float4 w1a = *(const float4*)(Wb + (k + 1) * LDW);
        float4 w1b = *(const float4*)(Wb + (k + 1) * LDW + 4);
        unsigned long long w0[4], w1[4];
        PACK2(w0[0], w0a.x, w0a.y); PACK2(w0[1], w0a.z, w0a.w);
        PACK2(w0[2], w0b.x, w0b.y); PACK2(w0[3], w0b.z, w0b.w);
        PACK2(w1[0], w1a.x, w1a.y); PACK2(w1[1], w1a.z, w1a.w);
        PACK2(w1[2], w1b.x, w1b.y); PACK2(w1[3], w1b.z, w1b.w);
#pragma unroll
        for (int i = 0; i < 8; i++) {
            unsigned long long a0, a1;
            PACK2(a0, a[i].x, a[i].x);
            PACK2(a1, a[i].y, a[i].y);
            FMA2(acc[i][0], a0, w0[0]);
            FMA2(acc[i][1], a0, w0[1]);
            FMA2(acc[i][2], a0, w0[2]);
            FMA2(acc[i][3], a0, w0[3]);
            FMA2(acc[i][0], a1, w1[0]);
            FMA2(acc[i][1], a1, w1[1]);
            FMA2(acc[i][2], a1, w1[2]);
            FMA2(acc[i][3], a1, w1[3]);
        }
    }

    // --- fused LSTM-cell epilogue ---
    const int nb = tx * 8;                   // first gate-col of this thread
#pragma unroll
    for (int i = 0; i < 8; i++) {
        long r = r0 + ty * 8 + i;
        int  b = (int)(r & (B_ - 1));        // row r = t*B + b
        float v[8];
#pragma unroll
        for (int p = 0; p < 4; p++) UNPACK2(v[2 * p], v[2 * p + 1], acc[i][p]);
        float hv[2], cv[2];
#pragma unroll
        for (int hh = 0; hh < 2; hh++) {
            const float* hb = HBs + b * NT + nb + hh * 4;
            float gi = v[hh * 4 + 0] + hb[0];
            float gf = v[hh * 4 + 1] + hb[1];
            float gg = v[hh * 4 + 2] + hb[2];
            float go = v[hh * 4 + 3] + hb[3];
            float si = 1.f / (1.f + expf(-gi));
            float sf = 1.f / (1.f + expf(-gf));
            float tg = tanhf(gg);
            float so = 1.f / (1.f + expf(-go));
            int hl = tx * 2 + hh;
            float c = sf * C0s[b * 32 + hl] + si * tg;
            cv[hh] = c;
            hv[hh] = so * tanhf(c) + NZs[b * 32 + hl];
        }
        float2 hp = make_float2(hv[0], hv[1]);
        long obase = r * H_ + ht * 32 + tx * 2;
        *(float2*)(out + obase) = hp;
        if (r >= (long)TB_ - B_) {           // last timestep: also h_last, c_last
            long lb = (long)TB_ * H_ + (long)b * H_ + ht * 32 + tx * 2;
            *(float2*)(out + lb) = hp;
            *(float2*)(out + lb + B_ * H_) = make_float2(cv[0], cv[1]);
        }
    }
}

// ---------------- launch ----------------
extern "C" void kernel_launch(void* const* d_in, const int* in_sizes, int n_in,
                              void* d_out, int out_size) {
    const float* input = (const float*)d_in[0];
    const float* h0    = (const float*)d_in[1];
    const float* c0    = (const float*)d_in[2];
    const float* noise = (const float*)d_in[3];
    const float* W_ih  = (const float*)d_in[4];
    const float* W_hh  = (const float*)d_in[5];
    const float* b_ih  = (const float*)d_in[6];
    const float* b_hh  = (const float*)d_in[7];
    float* out = (float*)d_out;

    prep_hb<<<B_, G4_>>>(h0, W_hh, b_ih, b_hh);
    prep_w<<<256, 256>>>(W_ih);

    const int smem = (MT * LDA + KD * LDW + B_ * NT + B_ * 32 + B_ * 32) * (int)sizeof(float);
    cudaFuncSetAttribute(lstm_main, cudaFuncAttributeMaxDynamicSharedMemorySize, smem);

    dim3 grid(4, TB_ / MT);   // 4 head tiles x 1024 row tiles
    lstm_main<<<grid, 256, smem>>>(input, c0, noise, out);
}

// round 5
// speedup vs baseline: 3.9088x; 3.9054x over previous
#include <cuda_runtime.h>
#include <cuda_fp16.h>
#include <cstdint>

#define TB_ 131072
#define B_  32

// ---------------- device scratch (no allocation allowed) ----------------
__device__ float g_hbre[B_ * 512];            // [b][nt*128 + hl*4 + q]
__device__ uint2 g_wfrag[4 * 16 * 8 * 32];    // [nt][nf][ks][lane] -> {b0,b1}

// ---------------- helpers ----------------
__device__ __forceinline__ uint32_t smem_u32(const void* p) {
    uint32_t a;
    asm("{ .reg .u64 t; cvta.to.shared.u64 t, %1; cvt.u32.u64 %0, t; }" : "=r"(a) : "l"(p));
    return a;
}
__device__ __forceinline__ float tanh_ap(float x) {
    float y; asm("tanh.approx.f32 %0, %1;" : "=f"(y) : "f"(x)); return y;
}
__device__ __forceinline__ float sig_ap(float x) { return fmaf(tanh_ap(x * 0.5f), 0.5f, 0.5f); }

// ---------------- prep: Hb = h0 @ W_hh^T + b_ih + b_hh (reordered) ----------------
__global__ void prep_hb(const float* __restrict__ h0, const float* __restrict__ W_hh,
                        const float* __restrict__ b_ih, const float* __restrict__ b_hh) {
    int idx = blockIdx.x * 256 + threadIdx.x;   // 0..16383
    int b = idx & 31, g = idx >> 5;
    const float4* wv = (const float4*)(W_hh + g * 128);
    const float4* hv = (const float4*)(h0 + b * 128);
    float s = b_ih[g] + b_hh[g];
#pragma unroll
    for (int k = 0; k < 32; k++) {
        float4 w = wv[k], h = hv[k];
        s += w.x * h.x + w.y * h.y + w.z * h.z + w.w * h.w;
    }
    int q = g >> 7, rest = g & 127, nt = rest >> 5, hl = rest & 31;
    g_hbre[b * 512 + nt * 128 + hl * 4 + q] = s;
}

// ---------------- prep: W_ih -> fp16 B-fragment-major ----------------
// mma.m16n8k16 B frag: b0 = {B[k0][n], B[k0+1][n]}, b1 = {B[k0+8][n], B[k0+9][n]},
// k0 = ks*16 + (lane&3)*2, n = nf*8 + (lane>>2).  Gate-interleaved n: n = hl*4 + q.
__global__ void prep_w(const float* __restrict__ W_ih) {
    int idx = blockIdx.x * 256 + threadIdx.x;   // 0..16383
    int l = idx & 31, ks = (idx >> 5) & 7, nf = (idx >> 8) & 15, nt = idx >> 12;
    int t = l & 3, gq = l >> 2;
    int n = nf * 8 + gq;
    int k0 = ks * 16 + t * 2;
    int g = (n & 3) * 128 + nt * 32 + (n >> 2);
    const float* wr = W_ih + g * 128;
    __half2 b0 = __floats2half2_rn(wr[k0], wr[k0 + 1]);
    __half2 b1 = __floats2half2_rn(wr[k0 + 8], wr[k0 + 9]);
    g_wfrag[idx] = make_uint2(*(uint32_t*)&b0, *(uint32_t*)&b1);
}

// ---------------- main kernel ----------------
#define SMEM_A   0                 // 32768 B : A fp16 swizzled (also Hs f32 stage in epilogue)
#define SMEM_B   32768             // 32768 B : B frags (uint2 x 4096)
#define SMEM_HB  65536             // 16896 B : HBs [32][132] f32
#define SMEM_C0  (65536 + 16896)   // 4224  B : c0   [32][33]
#define SMEM_NZ  (SMEM_C0 + 4224)  // 4224  B : noise[32][33]
#define SMEM_TOT (SMEM_NZ + 4224)  // 90880 B

__global__ __launch_bounds__(256, 2)
void lstm_mma(const float* __restrict__ input, const float* __restrict__ c0,
              const float* __restrict__ noise, float* __restrict__ out) {
    extern __shared__ char sm[];
    uint2* Bs  = (uint2*)(sm + SMEM_B);
    float* HBs = (float*)(sm + SMEM_HB);
    float* C0s = (float*)(sm + SMEM_C0);
    float* NZs = (float*)(sm + SMEM_NZ);
    float* Hs  = (float*)sm;               // aliases A region during epilogue

    const int tid = threadIdx.x;
    const int wid = tid >> 5, lane = tid & 31;
    const int nt = blockIdx.x & 3, grp = blockIdx.x >> 2;
    const int wm = wid & 1, wn = wid >> 1;            // 2 x 4 warp grid (64m x 32n tiles)
    const uint32_t smb = smem_u32(sm);

    // ---- stage B fragments, HB, c0, noise (once per CTA) ----
    {
        const uint2* src = g_wfrag + nt * 4096;
        for (int i = tid; i < 4096; i += 256) Bs[i] = src[i];
        for (int i = tid; i < 4096; i += 256) {
            int b = i >> 7, c = i & 127;
            HBs[b * 132 + c] = g_hbre[b * 512 + nt * 128 + c];
        }
        for (int i = tid; i < 1024; i += 256) {
            int b = i >> 5, hl = i & 31;
            C0s[b * 33 + hl] = c0[b * 128 + nt * 32 + hl];
            NZs[b * 33 + hl] = noise[b * 128 + nt * 32 + hl];
        }
    }

    // per-lane ldmatrix address pieces (A row-major fp16, 256B rows, 16B-chunk XOR swizzle)
    const int arow = lane & 15;                       // row within 16-row frag
    const uint32_t a_sw = (uint32_t)(arow & 7) << 4;  // swizzle (constant per lane)
    const uint32_t a_colb = (uint32_t)(lane >> 4) * 16;

    const int t = lane & 3, g = lane >> 2, odd = lane & 1;

    for (int it = 0; it < 4; it++) {
        const int mt = grp * 4 + it;
        const long r0 = (long)mt * 128;
        __syncthreads();                               // A/Hs buffer free

        // ---- load A tile: f32 -> fp16, swizzled STS ----
        {
            const float4* ip = (const float4*)(input + r0 * 128);
#pragma unroll
            for (int j = 0; j < 16; j++) {
                int i4 = tid + j * 256;                // row = i4>>5, q = i4&31
                int row = i4 >> 5, q = i4 & 31;
                float4 v = ip[i4];
                __half2 h0 = __floats2half2_rn(v.x, v.y);
                __half2 h1 = __floats2half2_rn(v.z, v.w);
                uint32_t off = (uint32_t)row * 256 + (((uint32_t)q * 8) ^ ((uint32_t)(row & 7) << 4));
                *(uint2*)(sm + SMEM_A + off) = make_uint2(*(uint32_t*)&h0, *(uint32_t*)&h1);
            }
        }
        __syncthreads();

        // ---- tensor-core GEMM: acc[mf][nf][4] ----
        float acc[4][4][4];
#pragma unroll
        for (int mf = 0; mf < 4; mf++)
#pragma unroll
            for (int nf = 0; nf < 4; nf++)
#pragma unroll
                for (int r = 0; r < 4; r++) acc[mf][nf][r] = 0.f;

#pragma unroll
        for (int ks = 0; ks < 8; ks++) {
            uint2 bfr[4];
#pragma unroll
            for (int nf = 0; nf < 4; nf++)
                bfr[nf] = Bs[((wn * 4 + nf) * 8 + ks) * 32 + lane];
#pragma unroll
            for (int mf = 0; mf < 4; mf++) {
                uint32_t row = (uint32_t)(wm * 64 + mf * 16 + arow);
                uint32_t addr = smb + SMEM_A + row * 256 + (((uint32_t)(ks * 32) + a_colb) ^ a_sw);
                uint32_t a0, a1, a2, a3;
                asm volatile("ldmatrix.sync.aligned.m8n8.x4.shared.b16 {%0,%1,%2,%3}, [%4];"
                             : "=r"(a0), "=r"(a1), "=r"(a2), "=r"(a3) : "r"(addr));
#pragma unroll
                for (int nf = 0; nf < 4; nf++) {
                    asm volatile(
                        "mma.sync.aligned.m16n8k16.row.col.f32.f16.f16.f32 "
                        "{%0,%1,%2,%3}, {%4,%5,%6,%7}, {%8,%9}, {%0,%1,%2,%3};"
                        : "+f"(acc[mf][nf][0]), "+f"(acc[mf][nf][1]),
                          "+f"(acc[mf][nf][2]), "+f"(acc[mf][nf][3])
                        : "r"(a0), "r"(a1), "r"(a2), "r"(a3),
                          "r"(bfr[nf].x), "r"(bfr[nf].y));
                }
            }
        }
        __syncthreads();                               // all A reads done; Hs may overwrite

        // ---- fused LSTM epilogue (shfl pairs -> 1 cell per lane per frag) ----
#pragma unroll
        for (int mf = 0; mf < 4; mf++) {
#pragma unroll
            for (int nf = 0; nf < 4; nf++) {
                float c0r = acc[mf][nf][0], c1r = acc[mf][nf][1];
                float c2r = acc[mf][nf][2], c3r = acc[mf][nf][3];
                float v0 = __shfl_xor_sync(0xffffffffu, c0r, 1);
                float v1 = __shfl_xor_sync(0xffffffffu, c1r, 1);
                float v2 = __shfl_xor_sync(0xffffffffu, c2r, 1);
                float v3 = __shfl_xor_sync(0xffffffffu, c3r, 1);
                float g0, g1, g2, g3;
                if (!odd) { g0 = c0r; g1 = c1r; g2 = v0; g3 = v1; }
                else      { g0 = v2;  g1 = v3;  g2 = c2r; g3 = c3r; }
                int row = wm * 64 + mf * 16 + g + (odd ? 8 : 0);
                int hl  = wn * 8 + nf * 2 + (t >> 1);
                int b   = row & 31;
                float4 hb = *(float4*)(HBs + b * 132 + hl * 4);
                float gi = g0 + hb.x, gf = g1 + hb.y, gg = g2 + hb.z, go = g3 + hb.w;
                float si = sig_ap(gi), sf = sig_ap(gf), so = sig_ap(go);
                float tg = tanh_ap(gg);
                float cc = sf * C0s[b * 33 + hl] + si * tg;
                float hv = so * tanh_ap(cc) + NZs[b * 33 + hl];
                Hs[row * 36 + hl] = hv;
                long gr = r0 + row;
                if (gr >= (long)TB_ - 32) {            // last timestep rows
                    long base = (long)TB_ * 128 + (long)b * 128 + nt * 32 + hl;
                    out[base] = hv;                    // h_last
                    out[base + 32 * 128] = cc;         // c_last
                }
            }
        }
        __syncthreads();

        // ---- coalesced store of h tile ----
#pragma unroll
        for (int j = 0; j < 4; j++) {
            int i4 = tid + j * 256;
            int row = i4 >> 3, hq = i4 & 7;
            float4 hv = *(float4*)(Hs + row * 36 + hq * 4);
            *(float4*)(out + (r0 + row) * 128 + nt * 32 + hq * 4) = hv;
        }
    }
}

// ---------------- launch ----------------
extern "C" void kernel_launch(void* const* d_in, const int* in_sizes, int n_in,
                              void* d_out, int out_size) {
    const float* input = (const float*)d_in[0];
    const float* h0    = (const float*)d_in[1];
    const float* c0    = (const float*)d_in[2];
    const float* noise = (const float*)d_in[3];
    const float* W_ih  = (const float*)d_in[4];
    const float* W_hh  = (const float*)d_in[5];
    const float* b_ih  = (const float*)d_in[6];
    const float* b_hh  = (const float*)d_in[7];
    float* out = (float*)d_out;

    prep_hb<<<64, 256>>>(h0, W_hh, b_ih, b_hh);
    prep_w<<<64, 256>>>(W_ih);

    cudaFuncSetAttribute(lstm_mma, cudaFuncAttributeMaxDynamicSharedMemorySize, SMEM_TOT);
    lstm_mma<<<1024, 256, SMEM_TOT>>>(input, c0, noise, out);
}